// round 2
// baseline (speedup 1.0000x reference)
#include <cuda_runtime.h>

#define DNUM 20
#define ONUM 19
#define MNUM 32
#define MM   (MNUM * MNUM)          // 1024 floats per C slab
#define NROWS (ONUM * ONUM * ONUM)  // 6859 (a,b,c) rows, 19 windows each
#define WPB 4
#define THREADS (WPB * 32)

// C[k][i][j] = cos(2*pi*k / (32*i + j + 2)), k in [0,19)
__device__ __align__(16) float g_C[ONUM * MM];

__global__ void init_tabs() {
    int t = blockIdx.x * blockDim.x + threadIdx.x;
    if (t < ONUM * MM) {
        int k = t / MM;
        int r = t % MM;                       // r = i*32 + j, period = r + 2
        g_C[t] = cosf(6.283185307179586f * (float)k / (float)(r + 2));
    }
}

// stream offsets (floats) within hypervol [20,20,20,20,32]:
// da:+256000  db:+12800  dc:+640  d-step:+32
#define COLSUM(ptr) ( __ldg(ptr)          + __ldg((ptr) + 640)    \
                    + __ldg((ptr) + 12800) + __ldg((ptr) + 13440) \
                    + __ldg((ptr) + 256000) + __ldg((ptr) + 256640) \
                    + __ldg((ptr) + 268800) + __ldg((ptr) + 269440) )

// One window step. CUR = t_d, OTH = t_{d+1}; after recurrence CUR becomes t_{d+2}.
#define BODY(CUR, OTH, ADV) {                                                  \
    float win = (cs0 + cs1) * 0.0625f;                                         \
    __syncwarp(); sWin[w][lane] = win; __syncwarp();                           \
    float x = 0.0f;                                                            \
    const float4* Wn4 = (const float4*)sWin[w];                                \
    _Pragma("unroll")                                                          \
    for (int kv = 0; kv < 8; ++kv) {                                           \
        float4 wv = Wn4[kv];                                                   \
        x = fmaf(Mrow[4*kv+0], wv.x, x);                                       \
        x = fmaf(Mrow[4*kv+1], wv.y, x);                                       \
        x = fmaf(Mrow[4*kv+2], wv.z, x);                                       \
        x = fmaf(Mrow[4*kv+3], wv.w, x);                                       \
    }                                                                          \
    __syncwarp(); sX[w][lane] = x; __syncwarp();                               \
    if (ADV) { cs0 = cs1; cs1 = COLSUM(hpre); hpre += MNUM; }                  \
    float acc = 0.0f;                                                          \
    const float4* X4 = (const float4*)sX[w];                                   \
    _Pragma("unroll")                                                          \
    for (int jv = 0; jv < 8; ++jv) {                                           \
        float4 xv = X4[jv];                                                    \
        acc = fmaf(xv.x, CUR[4*jv+0], acc);                                    \
        acc = fmaf(xv.y, CUR[4*jv+1], acc);                                    \
        acc = fmaf(xv.z, CUR[4*jv+2], acc);                                    \
        acc = fmaf(xv.w, CUR[4*jv+3], acc);                                    \
        if (ADV) {                                                             \
            CUR[4*jv+0] = fmaf(tc1[4*jv+0], OTH[4*jv+0], -CUR[4*jv+0]);        \
            CUR[4*jv+1] = fmaf(tc1[4*jv+1], OTH[4*jv+1], -CUR[4*jv+1]);        \
            CUR[4*jv+2] = fmaf(tc1[4*jv+2], OTH[4*jv+2], -CUR[4*jv+2]);        \
            CUR[4*jv+3] = fmaf(tc1[4*jv+3], OTH[4*jv+3], -CUR[4*jv+3]);        \
        }                                                                      \
    }                                                                          \
    *op = acc; op += MNUM;                                                     \
}

__global__ __launch_bounds__(THREADS, 3)
void sdd_main(const float* __restrict__ h, const float* __restrict__ Mw,
              const float* __restrict__ P, float* __restrict__ out) {
    __shared__ float sWin[WPB][MNUM];
    __shared__ float sX[WPB][MNUM];

    const int w = threadIdx.x >> 5, lane = threadIdx.x & 31;
    const int row = blockIdx.x * WPB + w;
    if (row >= NROWS) return;

    const int a = row / (ONUM * ONUM);
    const int bc = row - a * (ONUM * ONUM);
    const int b = bc / ONUM;
    const int c = bc - b * ONUM;

    // Per-lane constants: M_w row (lane = output index) and 2*cos(theta_ij) (lane = i)
    float Mrow[MNUM], tc1[MNUM];
    {
        const float4* M4 = (const float4*)Mw + lane * 8;
        const float4* T4 = (const float4*)(g_C + MM) + lane * 8;   // k=1 slab
#pragma unroll
        for (int v4 = 0; v4 < 8; ++v4) {
            float4 mv = __ldg(M4 + v4);
            Mrow[4*v4+0] = mv.x; Mrow[4*v4+1] = mv.y;
            Mrow[4*v4+2] = mv.z; Mrow[4*v4+3] = mv.w;
            float4 tv = __ldg(T4 + v4);
            tc1[4*v4+0] = 2.0f * tv.x; tc1[4*v4+1] = 2.0f * tv.y;
            tc1[4*v4+2] = 2.0f * tv.z; tc1[4*v4+3] = 2.0f * tv.w;
        }
    }

    // Row setup: u = t_0 = P .* C[a] .* C[b] .* C[c];  v = t_1 = u .* cos(theta)
    float u[MNUM], v[MNUM];
    {
        const float4* P4 = (const float4*)P + lane * 8;
        const float4* A4 = (const float4*)g_C + a * (MM / 4) + lane * 8;
        const float4* B4 = (const float4*)g_C + b * (MM / 4) + lane * 8;
        const float4* C4 = (const float4*)g_C + c * (MM / 4) + lane * 8;
#pragma unroll
        for (int v4 = 0; v4 < 8; ++v4) {
            float4 pv = __ldg(P4 + v4), av = __ldg(A4 + v4);
            float4 bv = __ldg(B4 + v4), cv = __ldg(C4 + v4);
            u[4*v4+0] = pv.x * av.x * bv.x * cv.x;
            u[4*v4+1] = pv.y * av.y * bv.y * cv.y;
            u[4*v4+2] = pv.z * av.z * bv.z * cv.z;
            u[4*v4+3] = pv.w * av.w * bv.w * cv.w;
            v[4*v4+0] = u[4*v4+0] * (0.5f * tc1[4*v4+0]);
            v[4*v4+1] = u[4*v4+1] * (0.5f * tc1[4*v4+1]);
            v[4*v4+2] = u[4*v4+2] * (0.5f * tc1[4*v4+2]);
            v[4*v4+3] = u[4*v4+3] * (0.5f * tc1[4*v4+3]);
        }
    }

    // Window-mean column sums with d-chaining
    const float* hb = h + (((a * DNUM + b) * DNUM + c) * DNUM) * MNUM + lane;
    float cs0 = COLSUM(hb);
    float cs1 = COLSUM(hb + MNUM);
    const float* hpre = hb + 2 * MNUM;
    float* op = out + row * (ONUM * MNUM) + lane;

    // d = 0..17 (paired, with recurrence + prefetch), then d = 18 tail
#pragma unroll 1
    for (int it = 0; it < 9; ++it) {
        BODY(u, v, 1);
        BODY(v, u, 1);
    }
    BODY(u, v, 0);
}

extern "C" void kernel_launch(void* const* d_in, const int* in_sizes, int n_in,
                              void* d_out, int out_size) {
    const float* h  = (const float*)d_in[0];   // hypervol [20,20,20,20,32]
    const float* Mw = (const float*)d_in[1];   // M_w [32,32]
    const float* P  = (const float*)d_in[2];   // P  [32,32]
    float* out = (float*)d_out;                // [130321, 32]

    init_tabs<<<(ONUM * MM + 511) / 512, 512>>>();
    sdd_main<<<(NROWS + WPB - 1) / WPB, THREADS>>>(h, Mw, P, out);
}